// round 11
// baseline (speedup 1.0000x reference)
#include <cuda_runtime.h>
#include <cuda_bf16.h>
#include <cstdint>

// Problem constants (Wisard_68401649156855)
#define ENTRY_SIZE 1024
#define N_CLASSES  10
#define TUPLE_SIZE 16
#define N_RAMS     64
#define N_ADDR     65536
#define BATCH      8192
#define WORDS_PER_ROW 32

#define GROUPS_PER_BLOCK 4      // 4 x 32 = 128 samples per block

// Scratch: transposed packed sample bits, bitsT[w][b]
// bit k of bitsT[w][b] = samples[b][w*32+k]
__device__ unsigned g_bitsT[WORDS_PER_ROW * BATCH];

// ---------------------------------------------------------------------------
// Kernel 1: pack samples (int32 0/1) -> bit matrix. (unchanged, known correct)
// ---------------------------------------------------------------------------
__global__ void __launch_bounds__(256) wisard_pack_kernel(const int* __restrict__ samples)
{
    int gtid   = blockIdx.x * blockDim.x + threadIdx.x;
    int b      = gtid >> 5;            // warp = sample row
    int lane   = gtid & 31;

    const int4* base = (const int4*)(samples + (size_t)b * ENTRY_SIZE) + lane;
    int4 v[8];
    #pragma unroll
    for (int it = 0; it < 8; ++it)
        v[it] = base[it * 32];

    unsigned j   = lane >> 3;
    unsigned sh  = 4u * (lane & 7);

    #pragma unroll
    for (int it = 0; it < 8; ++it) {
        unsigned nib = (unsigned)(v[it].x != 0)
                     | ((unsigned)(v[it].y != 0) << 1)
                     | ((unsigned)(v[it].z != 0) << 2)
                     | ((unsigned)(v[it].w != 0) << 3);
        unsigned x = nib << sh;
        x |= __shfl_xor_sync(0xffffffffu, x, 1);
        x |= __shfl_xor_sync(0xffffffffu, x, 2);
        x |= __shfl_xor_sync(0xffffffffu, x, 4);
        if ((lane & 7) == 0)
            g_bitsT[(it * 4 + j) * BATCH + b] = x;
    }
}

// ---------------------------------------------------------------------------
// 32x32 bit-matrix transpose across a warp (block-swap butterfly).
// out lane j, bit k  =  in lane k, bit j.
// ---------------------------------------------------------------------------
__device__ __forceinline__ unsigned warp_bit_transpose(unsigned x, int lane)
{
    const unsigned masks[5] = { 0x0000FFFFu, 0x00FF00FFu, 0x0F0F0F0Fu,
                                0x33333333u, 0x55555555u };
    const int shifts[5] = { 16, 8, 4, 2, 1 };
    #pragma unroll
    for (int i = 0; i < 5; ++i) {
        int s = shifts[i];
        unsigned lm = masks[i];
        unsigned y = __shfl_xor_sync(0xffffffffu, x, s);
        if ((lane & s) == 0)
            x = (x & lm) | ((y & lm) << s);
        else
            x = (x & ~lm) | ((y & ~lm) >> s);
    }
    return x;
}

// ---------------------------------------------------------------------------
// Kernel 2: main WiSARD lookup, 4 sample-groups per block for MLP.
// Grid: (BATCH/128, N_CLASSES). Block: 256 threads = 8 warps.
// Phase 1: 128 tile-transposes -> bitS_s[g][e] entry-major words (16/warp).
// Phase 2a: warp wid owns RAMs [wid*8, wid*8+8). For each RAM pair, load the
//   permuted tuple-entry word ONCE per group, transpose -> lane j holds
//   (addr_{r+1}<<16)|addr_r for sample j of group g. 16 transposes/warp.
// Phase 2b: 32 independent gathers back-to-back per warp (MLP=32).
// Phase 3: cross-warp reduction per group.
// ---------------------------------------------------------------------------
__global__ void __launch_bounds__(256) wisard_main_kernel(
    const int*   __restrict__ tuple_mapping,  // [N_CLASSES][ENTRY_SIZE]
    const float* __restrict__ ram_table,      // [N_CLASSES][N_RAMS][N_ADDR]
    float*       __restrict__ out)            // [BATCH][N_CLASSES]
{
    const int c    = blockIdx.y;
    const int bw   = blockIdx.x;               // 128-sample super-group
    const int tid  = threadIdx.x;
    const int wid  = tid >> 5;
    const int lane = tid & 31;

    __shared__ __align__(16) int tm_s[ENTRY_SIZE];                       // 4 KB
    __shared__ unsigned          bitS_s[GROUPS_PER_BLOCK * ENTRY_SIZE];  // 16 KB
    __shared__ float             red[8][GROUPS_PER_BLOCK][32];           // 4 KB

    #pragma unroll
    for (int i = 0; i < ENTRY_SIZE / 256; ++i)
        tm_s[tid + i * 256] = tuple_mapping[c * ENTRY_SIZE + tid + i * 256];

    // Phase 1: entry-major sample-bit words, 4 groups.
    const int sbase = bw * (GROUPS_PER_BLOCK * 32);
    #pragma unroll
    for (int k = 0; k < 4; ++k) {
        int w = wid * 4 + k;
        #pragma unroll
        for (int g = 0; g < GROUPS_PER_BLOCK; ++g) {
            unsigned x = g_bitsT[w * BATCH + sbase + g * 32 + lane];
            x = warp_bit_transpose(x, lane);
            bitS_s[g * ENTRY_SIZE + w * 32 + lane] = x;
        }
    }

    __syncthreads();

    const float* tbl = ram_table + (size_t)c * (N_RAMS * N_ADDR);

    // lane l -> tuple slot (r + (l>>4))*16 + 15 - (l&15)
    const int tm_off = (lane >> 4) * 16 + 15 - (lane & 15);

    // Phase 2a: 16 transposes -> 32 addresses (2 per word) across 4 groups.
    unsigned aw[4][GROUPS_PER_BLOCK];
    #pragma unroll
    for (int pair = 0; pair < 4; ++pair) {
        const int r = wid * 8 + pair * 2;
        const int idx = tm_s[r * 16 + tm_off];       // shared across groups
        #pragma unroll
        for (int g = 0; g < GROUPS_PER_BLOCK; ++g)
            aw[pair][g] = warp_bit_transpose(bitS_s[g * ENTRY_SIZE + idx], lane);
    }

    // Phase 2b: 32 independent gathers (lane = sample within group).
    float acc[GROUPS_PER_BLOCK] = {0.f, 0.f, 0.f, 0.f};
    #pragma unroll
    for (int pair = 0; pair < 4; ++pair) {
        const int r = wid * 8 + pair * 2;
        const float* base = tbl + ((size_t)r << TUPLE_SIZE);
        #pragma unroll
        for (int g = 0; g < GROUPS_PER_BLOCK; ++g) {
            float v0 = __ldg(base + (aw[pair][g] & 0xFFFFu));
            float v1 = __ldg(base + N_ADDR + (aw[pair][g] >> 16));
            acc[g] += v0 + v1;
        }
    }

    // Phase 3: reduce the 8 warp partials per (group, sample).
    #pragma unroll
    for (int g = 0; g < GROUPS_PER_BLOCK; ++g)
        red[wid][g][lane] = acc[g];
    __syncthreads();

    if (wid < GROUPS_PER_BLOCK) {
        // warp wid reduces group wid
        float s = red[0][wid][lane];
        #pragma unroll
        for (int w = 1; w < 8; ++w) s += red[w][wid][lane];
        out[(sbase + wid * 32 + lane) * N_CLASSES + c] = s;
    }
}

// ---------------------------------------------------------------------------
// Launch
// ---------------------------------------------------------------------------
extern "C" void kernel_launch(void* const* d_in, const int* in_sizes, int n_in,
                              void* d_out, int out_size)
{
    const int*   samples       = (const int*)  d_in[0];  // [8192][1024] int32
    const int*   tuple_mapping = (const int*)  d_in[1];  // [10][1024]   int32
    const float* ram_table     = (const float*)d_in[2];  // [10][64][65536] float32
    float*       out           = (float*)d_out;          // [8192][10]   float32

    wisard_pack_kernel<<<(BATCH * 32) / 256, 256>>>(samples);

    dim3 grid(BATCH / (GROUPS_PER_BLOCK * 32), N_CLASSES);  // 64 x 10 = 640 blocks
    wisard_main_kernel<<<grid, 256>>>(tuple_mapping, ram_table, out);
}

// round 14
// speedup vs baseline: 2.7464x; 2.7464x over previous
#include <cuda_runtime.h>
#include <cuda_bf16.h>
#include <cstdint>

// Problem constants (Wisard_68401649156855)
#define ENTRY_SIZE 1024
#define N_CLASSES  10
#define TUPLE_SIZE 16
#define N_RAMS     64
#define N_ADDR     65536
#define BATCH      8192
#define WORDS_PER_ROW 32

#define GPB 2                   // groups of 32 samples per block (64 samples)

// Scratch: transposed packed sample bits, bitsT[w][b]
// bit k of bitsT[w][b] = samples[b][w*32+k]
__device__ unsigned g_bitsT[WORDS_PER_ROW * BATCH];

// ---------------------------------------------------------------------------
// Kernel 1: pack samples (int32 0/1) -> bit matrix. (unchanged, known correct)
// ---------------------------------------------------------------------------
__global__ void __launch_bounds__(256) wisard_pack_kernel(const int* __restrict__ samples)
{
    int gtid   = blockIdx.x * blockDim.x + threadIdx.x;
    int b      = gtid >> 5;            // warp = sample row
    int lane   = gtid & 31;

    const int4* base = (const int4*)(samples + (size_t)b * ENTRY_SIZE) + lane;
    int4 v[8];
    #pragma unroll
    for (int it = 0; it < 8; ++it)
        v[it] = base[it * 32];

    unsigned j   = lane >> 3;
    unsigned sh  = 4u * (lane & 7);

    #pragma unroll
    for (int it = 0; it < 8; ++it) {
        unsigned nib = (unsigned)(v[it].x != 0)
                     | ((unsigned)(v[it].y != 0) << 1)
                     | ((unsigned)(v[it].z != 0) << 2)
                     | ((unsigned)(v[it].w != 0) << 3);
        unsigned x = nib << sh;
        x |= __shfl_xor_sync(0xffffffffu, x, 1);
        x |= __shfl_xor_sync(0xffffffffu, x, 2);
        x |= __shfl_xor_sync(0xffffffffu, x, 4);
        if ((lane & 7) == 0)
            g_bitsT[(it * 4 + j) * BATCH + b] = x;
    }
}

// ---------------------------------------------------------------------------
// 32x32 bit-matrix transpose across a warp (block-swap butterfly).
// out lane j, bit k  =  in lane k, bit j.
// ---------------------------------------------------------------------------
__device__ __forceinline__ unsigned warp_bit_transpose(unsigned x, int lane)
{
    const unsigned masks[5] = { 0x0000FFFFu, 0x00FF00FFu, 0x0F0F0F0Fu,
                                0x33333333u, 0x55555555u };
    const int shifts[5] = { 16, 8, 4, 2, 1 };
    #pragma unroll
    for (int i = 0; i < 5; ++i) {
        int s = shifts[i];
        unsigned lm = masks[i];
        unsigned y = __shfl_xor_sync(0xffffffffu, x, s);
        if ((lane & s) == 0)
            x = (x & lm) | ((y & lm) << s);
        else
            x = (x & ~lm) | ((y & ~lm) >> s);
    }
    return x;
}

// ---------------------------------------------------------------------------
// Kernel 2: main WiSARD lookup, 2 sample-groups per block (MLP=16/warp).
// Grid: (BATCH/64, N_CLASSES) = 1280 blocks. Block: 256 threads = 8 warps.
// Phase 1: tile-transposes -> bitS_s[g][e] entry-major words (8/warp).
// Phase 2a: warp wid owns RAMs [wid*8, wid*8+8). Per RAM pair, load the
//   permuted tuple-entry word (idx shared across groups), transpose ->
//   lane j holds (addr_{r+1}<<16)|addr_r for sample j of group g.
// Phase 2b: 16 independent gathers back-to-back per warp.
// Phase 3: cross-warp reduction per group.
// __launch_bounds__(256, 4): allow up to 64 regs -> no local spills of aw[].
// ---------------------------------------------------------------------------
__global__ void __launch_bounds__(256, 4) wisard_main_kernel(
    const int*   __restrict__ tuple_mapping,  // [N_CLASSES][ENTRY_SIZE]
    const float* __restrict__ ram_table,      // [N_CLASSES][N_RAMS][N_ADDR]
    float*       __restrict__ out)            // [BATCH][N_CLASSES]
{
    const int c    = blockIdx.y;
    const int bw   = blockIdx.x;               // 64-sample super-group
    const int tid  = threadIdx.x;
    const int wid  = tid >> 5;
    const int lane = tid & 31;

    __shared__ __align__(16) int tm_s[ENTRY_SIZE];          // 4 KB
    __shared__ unsigned          bitS_s[GPB * ENTRY_SIZE];  // 8 KB
    __shared__ float             red[8][GPB][32];           // 2 KB

    #pragma unroll
    for (int i = 0; i < ENTRY_SIZE / 256; ++i)
        tm_s[tid + i * 256] = tuple_mapping[c * ENTRY_SIZE + tid + i * 256];

    // Phase 1: entry-major sample-bit words, 2 groups.
    const int sbase = bw * (GPB * 32);
    #pragma unroll
    for (int k = 0; k < 4; ++k) {
        int w = wid * 4 + k;
        #pragma unroll
        for (int g = 0; g < GPB; ++g) {
            unsigned x = g_bitsT[w * BATCH + sbase + g * 32 + lane];
            x = warp_bit_transpose(x, lane);
            bitS_s[g * ENTRY_SIZE + w * 32 + lane] = x;
        }
    }

    __syncthreads();

    const float* tbl = ram_table + (size_t)c * (N_RAMS * N_ADDR);

    // lane l -> tuple slot (r + (l>>4))*16 + 15 - (l&15)
    const int tm_off = (lane >> 4) * 16 + 15 - (lane & 15);

    // Phase 2a: 8 transposes -> 16 addresses (2 per word) across 2 groups.
    unsigned aw[4][GPB];
    #pragma unroll
    for (int pair = 0; pair < 4; ++pair) {
        const int r = wid * 8 + pair * 2;
        const int idx = tm_s[r * 16 + tm_off];       // shared across groups
        #pragma unroll
        for (int g = 0; g < GPB; ++g)
            aw[pair][g] = warp_bit_transpose(bitS_s[g * ENTRY_SIZE + idx], lane);
    }

    // Phase 2b: 16 independent gathers (lane = sample within group).
    float acc[GPB] = {0.f, 0.f};
    #pragma unroll
    for (int pair = 0; pair < 4; ++pair) {
        const int r = wid * 8 + pair * 2;
        const float* base = tbl + ((size_t)r << TUPLE_SIZE);
        #pragma unroll
        for (int g = 0; g < GPB; ++g) {
            float v0 = __ldg(base + (aw[pair][g] & 0xFFFFu));
            float v1 = __ldg(base + N_ADDR + (aw[pair][g] >> 16));
            acc[g] += v0 + v1;
        }
    }

    // Phase 3: reduce the 8 warp partials per (group, sample).
    #pragma unroll
    for (int g = 0; g < GPB; ++g)
        red[wid][g][lane] = acc[g];
    __syncthreads();

    if (wid < GPB) {
        float s = red[0][wid][lane];
        #pragma unroll
        for (int w = 1; w < 8; ++w) s += red[w][wid][lane];
        out[(sbase + wid * 32 + lane) * N_CLASSES + c] = s;
    }
}

// ---------------------------------------------------------------------------
// Launch
// ---------------------------------------------------------------------------
extern "C" void kernel_launch(void* const* d_in, const int* in_sizes, int n_in,
                              void* d_out, int out_size)
{
    const int*   samples       = (const int*)  d_in[0];  // [8192][1024] int32
    const int*   tuple_mapping = (const int*)  d_in[1];  // [10][1024]   int32
    const float* ram_table     = (const float*)d_in[2];  // [10][64][65536] float32
    float*       out           = (float*)d_out;          // [8192][10]   float32

    wisard_pack_kernel<<<(BATCH * 32) / 256, 256>>>(samples);

    dim3 grid(BATCH / (GPB * 32), N_CLASSES);   // 128 x 10 = 1280 blocks
    wisard_main_kernel<<<grid, 256>>>(tuple_mapping, ram_table, out);
}